// round 2
// baseline (speedup 1.0000x reference)
#include <cuda_runtime.h>

// Problem constants
#define NB   64
#define CCH  1024
#define HW   1024
#define SIZE 32
#define CS   8              // channel split for parallelism
#define CPS  (CCH / CS)     // channels per split = 128

// Device scratch (no allocations allowed)
__device__ float g_partial[NB * CS * HW];   // 2 MB
__device__ float g_reduced[NB * HW];        // 256 KB

// Output layout (float32, tuple members flattened + concatenated)
#define OFF_RCT    0                         // relative_coord_total [N,HW,2]
#define OFF_ANCHOR (NB * HW * 2)             // basic_anchor [N,2]         = 131072
#define OFF_PW     (OFF_ANCHOR + NB * 2)     // position_weight [N,HW,HW]  = 131200
#define OFF_IDX    (OFF_PW + (size_t)NB * HW * HW) // reduced_x_max_index [N] = 67240064

// ---------------------------------------------------------------------------
// Kernel 1: partial channel sums. Block (n, s) sums 128 channels for all 1024
// spatial positions. Coalesced: thread j reads x[n, c, j] (contiguous in j).
// ---------------------------------------------------------------------------
__global__ void __launch_bounds__(1024, 2)
k_chansum(const float* __restrict__ x) {
    const int n = blockIdx.x;
    const int s = blockIdx.y;
    const int j = threadIdx.x;
    const float* p = x + ((size_t)n * CCH + (size_t)s * CPS) * HW + j;

    float a0 = 0.f, a1 = 0.f, a2 = 0.f, a3 = 0.f;
#pragma unroll 8
    for (int c = 0; c < CPS; c += 4) {
        a0 += p[(size_t)(c + 0) * HW];
        a1 += p[(size_t)(c + 1) * HW];
        a2 += p[(size_t)(c + 2) * HW];
        a3 += p[(size_t)(c + 3) * HW];
    }
    g_partial[(n * CS + s) * HW + j] = (a0 + a1) + (a2 + a3);
}

// ---------------------------------------------------------------------------
// Kernel 2: per-sample stats. One block of 1024 threads per sample.
// mask -> threshold (mean) -> binary -> reduced -> argmax (first occurrence)
// -> relative dist/angle outputs + anchor + index.
// ---------------------------------------------------------------------------
__global__ void __launch_bounds__(1024, 1)
k_stats(float* __restrict__ out) {
    const int n = blockIdx.x;
    const int j = threadIdx.x;

    __shared__ float sval[HW];
    __shared__ int   sidx[HW];

    // combine partials (deterministic order)
    float m = 0.f;
#pragma unroll
    for (int s = 0; s < CS; s++)
        m += g_partial[(n * CS + s) * HW + j];

    // threshold = mean over HW
    sval[j] = m;
    __syncthreads();
#pragma unroll
    for (int st = HW / 2; st > 0; st >>= 1) {
        if (j < st) sval[j] += sval[j + st];
        __syncthreads();
    }
    const float thr = sval[0] * (1.0f / HW);
    __syncthreads();

    const float bin = (m > thr) ? 1.0f : 0.0f;
    const float red = bin * m * (1.0f / CCH);   // mean over channels of masked x
    g_reduced[n * HW + j] = red;

    // argmax with first-occurrence tie-break
    sval[j] = red;
    sidx[j] = j;
    __syncthreads();
#pragma unroll
    for (int st = HW / 2; st > 0; st >>= 1) {
        if (j < st) {
            float v2 = sval[j + st];
            int   i2 = sidx[j + st];
            if (v2 > sval[j] || (v2 == sval[j] && i2 < sidx[j])) {
                sval[j] = v2;
                sidx[j] = i2;
            }
        }
        __syncthreads();
    }
    const int amax = sidx[0];

    const float ar = (float)(amax >> 5);   // anchor row
    const float ac = (float)(amax & 31);   // anchor col

    const float r0 = ((float)(j >> 5) - ar) * (1.0f / SIZE);
    const float r1 = ((float)(j & 31) - ac) * (1.0f / SIZE);
    const float dist = sqrtf(r0 * r0 + r1 * r1) * bin;
    // angle * (0.5/pi) + 0.5, then masked
    const float ang = (atan2f(r1, r0) * 0.15915494309189535f + 0.5f) * bin;

    out[OFF_RCT + ((size_t)n * HW + j) * 2 + 0] = dist;
    out[OFF_RCT + ((size_t)n * HW + j) * 2 + 1] = ang;

    if (j == 0) {
        out[OFF_ANCHOR + n * 2 + 0] = ar;
        out[OFF_ANCHOR + n * 2 + 1] = ac;
        out[OFF_IDX + n]            = (float)amax;
    }
}

// ---------------------------------------------------------------------------
// Kernel 3: position_weight[n,i,j] = reduced[n,i] * reduced[n,j].
// Block handles 16 rows of one sample. reduced[n,:] staged in smem, float4
// stores (64 KB written per block). Pure write bandwidth.
// ---------------------------------------------------------------------------
#define ROWS_PER_BLK 16
__global__ void __launch_bounds__(256, 8)
k_outer(float* __restrict__ out) {
    const int n  = blockIdx.y;
    const int rb = blockIdx.x;            // row-tile: rows [rb*16, rb*16+16)
    const int t  = threadIdx.x;           // 0..255

    __shared__ float sred[HW];
#pragma unroll
    for (int k = 0; k < 4; k++)
        sred[t + 256 * k] = g_reduced[n * HW + t + 256 * k];
    __syncthreads();

    const float4 s4 = ((const float4*)sred)[t];
    float4* o = (float4*)(out + OFF_PW + ((size_t)n * HW + (size_t)rb * ROWS_PER_BLK) * HW);

#pragma unroll
    for (int r = 0; r < ROWS_PER_BLK; r++) {
        const float ri = sred[rb * ROWS_PER_BLK + r];
        float4 v;
        v.x = ri * s4.x;
        v.y = ri * s4.y;
        v.z = ri * s4.z;
        v.w = ri * s4.w;
        o[(size_t)r * (HW / 4) + t] = v;
    }
}

// ---------------------------------------------------------------------------
extern "C" void kernel_launch(void* const* d_in, const int* in_sizes, int n_in,
                              void* d_out, int out_size) {
    const float* x = (const float*)d_in[0];
    float* out = (float*)d_out;

    {
        dim3 grid(NB, CS);
        k_chansum<<<grid, 1024>>>(x);
    }
    k_stats<<<NB, 1024>>>(out);
    {
        dim3 grid(HW / ROWS_PER_BLK, NB);   // (64, 64)
        k_outer<<<grid, 256>>>(out);
    }
}

// round 3
// speedup vs baseline: 1.0379x; 1.0379x over previous
#include <cuda_runtime.h>

// Problem constants
#define NB   64
#define CCH  1024
#define HW   1024
#define SIZE 32
#define CS   8              // channel split for parallelism
#define CPS  (CCH / CS)     // channels per split = 128

// Device scratch (no allocations allowed)
__device__ float g_partial[NB * CS * HW];   // 2 MB
__device__ float g_reduced[NB * HW];        // 256 KB

// Output layout (float32, tuple members flattened + concatenated)
#define OFF_RCT    0                         // relative_coord_total [N,HW,2]
#define OFF_ANCHOR (NB * HW * 2)             // basic_anchor [N,2]
#define OFF_PW     (OFF_ANCHOR + NB * 2)     // position_weight [N,HW,HW]
#define OFF_IDX    (OFF_PW + (size_t)NB * HW * HW) // reduced_x_max_index [N]

// ---------------------------------------------------------------------------
// Kernel 1: partial channel sums, vectorized. Block (n, s): 256 threads, each
// owns 4 consecutive j (one float4 column group) and sums 128 channels.
// 4 independent float4 accumulators -> 4+ LDG.128 in flight per thread.
// ---------------------------------------------------------------------------
__global__ void __launch_bounds__(256, 6)
k_chansum(const float* __restrict__ x) {
    const int n = blockIdx.x;
    const int s = blockIdx.y;
    const int t = threadIdx.x;                 // 0..255
    const float4* __restrict__ p =
        (const float4*)(x + ((size_t)n * CCH + (size_t)s * CPS) * HW) + t;

    float4 a0 = make_float4(0.f, 0.f, 0.f, 0.f);
    float4 a1 = a0, a2 = a0, a3 = a0;

#pragma unroll 4
    for (int c = 0; c < CPS; c += 4) {
        const float4 v0 = p[(size_t)(c + 0) * (HW / 4)];
        const float4 v1 = p[(size_t)(c + 1) * (HW / 4)];
        const float4 v2 = p[(size_t)(c + 2) * (HW / 4)];
        const float4 v3 = p[(size_t)(c + 3) * (HW / 4)];
        a0.x += v0.x; a0.y += v0.y; a0.z += v0.z; a0.w += v0.w;
        a1.x += v1.x; a1.y += v1.y; a1.z += v1.z; a1.w += v1.w;
        a2.x += v2.x; a2.y += v2.y; a2.z += v2.z; a2.w += v2.w;
        a3.x += v3.x; a3.y += v3.y; a3.z += v3.z; a3.w += v3.w;
    }
    float4 r;
    r.x = (a0.x + a1.x) + (a2.x + a3.x);
    r.y = (a0.y + a1.y) + (a2.y + a3.y);
    r.z = (a0.z + a1.z) + (a2.z + a3.z);
    r.w = (a0.w + a1.w) + (a2.w + a3.w);
    ((float4*)g_partial)[(size_t)(n * CS + s) * (HW / 4) + t] = r;
}

// ---------------------------------------------------------------------------
// Kernel 2: per-sample stats. One block of 1024 threads per sample.
// ---------------------------------------------------------------------------
__global__ void __launch_bounds__(1024, 1)
k_stats(float* __restrict__ out) {
    const int n = blockIdx.x;
    const int j = threadIdx.x;

    __shared__ float sval[HW];
    __shared__ int   sidx[HW];

    // combine partials (deterministic order)
    float m = 0.f;
#pragma unroll
    for (int s = 0; s < CS; s++)
        m += g_partial[(n * CS + s) * HW + j];

    // threshold = mean over HW
    sval[j] = m;
    __syncthreads();
#pragma unroll
    for (int st = HW / 2; st > 0; st >>= 1) {
        if (j < st) sval[j] += sval[j + st];
        __syncthreads();
    }
    const float thr = sval[0] * (1.0f / HW);
    __syncthreads();

    const float bin = (m > thr) ? 1.0f : 0.0f;
    const float red = bin * m * (1.0f / CCH);
    g_reduced[n * HW + j] = red;

    // argmax with first-occurrence tie-break
    sval[j] = red;
    sidx[j] = j;
    __syncthreads();
#pragma unroll
    for (int st = HW / 2; st > 0; st >>= 1) {
        if (j < st) {
            float v2 = sval[j + st];
            int   i2 = sidx[j + st];
            if (v2 > sval[j] || (v2 == sval[j] && i2 < sidx[j])) {
                sval[j] = v2;
                sidx[j] = i2;
            }
        }
        __syncthreads();
    }
    const int amax = sidx[0];

    const float ar = (float)(amax >> 5);
    const float ac = (float)(amax & 31);

    const float r0 = ((float)(j >> 5) - ar) * (1.0f / SIZE);
    const float r1 = ((float)(j & 31) - ac) * (1.0f / SIZE);
    const float dist = sqrtf(r0 * r0 + r1 * r1) * bin;
    const float ang = (atan2f(r1, r0) * 0.15915494309189535f + 0.5f) * bin;

    out[OFF_RCT + ((size_t)n * HW + j) * 2 + 0] = dist;
    out[OFF_RCT + ((size_t)n * HW + j) * 2 + 1] = ang;

    if (j == 0) {
        out[OFF_ANCHOR + n * 2 + 0] = ar;
        out[OFF_ANCHOR + n * 2 + 1] = ac;
        out[OFF_IDX + n]            = (float)amax;
    }
}

// ---------------------------------------------------------------------------
// Kernel 3: position_weight[n,i,j] = reduced[n,i] * reduced[n,j].
// 16 rows per block, streaming (evict-first) 128-bit stores: the 268 MB output
// is write-once and >2x L2, so keep it out of cache.
// ---------------------------------------------------------------------------
#define ROWS_PER_BLK 16
__global__ void __launch_bounds__(256, 8)
k_outer(float* __restrict__ out) {
    const int n  = blockIdx.y;
    const int rb = blockIdx.x;
    const int t  = threadIdx.x;

    __shared__ float sred[HW];
#pragma unroll
    for (int k = 0; k < 4; k++)
        sred[t + 256 * k] = g_reduced[n * HW + t + 256 * k];
    __syncthreads();

    const float4 s4 = ((const float4*)sred)[t];
    float4* o = (float4*)(out + OFF_PW + ((size_t)n * HW + (size_t)rb * ROWS_PER_BLK) * HW);

#pragma unroll
    for (int r = 0; r < ROWS_PER_BLK; r++) {
        const float ri = sred[rb * ROWS_PER_BLK + r];
        float4 v;
        v.x = ri * s4.x;
        v.y = ri * s4.y;
        v.z = ri * s4.z;
        v.w = ri * s4.w;
        __stcs(o + (size_t)r * (HW / 4) + t, v);
    }
}

// ---------------------------------------------------------------------------
extern "C" void kernel_launch(void* const* d_in, const int* in_sizes, int n_in,
                              void* d_out, int out_size) {
    const float* x = (const float*)d_in[0];
    float* out = (float*)d_out;

    {
        dim3 grid(NB, CS);
        k_chansum<<<grid, 256>>>(x);
    }
    k_stats<<<NB, 1024>>>(out);
    {
        dim3 grid(HW / ROWS_PER_BLK, NB);
        k_outer<<<grid, 256>>>(out);
    }
}